// round 7
// baseline (speedup 1.0000x reference)
#include <cuda_runtime.h>
#include <math.h>

#define Bv 32
#define Cv 1024
#define BC_TOTAL (Bv * Cv)      // 32768
#define HW 784                  // 28*28
#define NMASK 154               // 153 masks + 1 global-max term
#define K1_BLOCKS 512           // 64 channels per block
#define SXPITCH 113             // words per channel row in staging (odd -> conflict-free)
#define NST 78                  // state floats per (b,c): center, gm, 76 rings

// ---- static device scratch (no allocations allowed) ----
__device__ float g_st[NST * BC_TOTAL];        // compact state, ~10.2 MB
__device__ float g_sqpart[NMASK * K1_BLOCKS]; // per-block partial squared sums

// ------------------------------------------------------------------
// Compile-time per-(quadrant, tile) pixel lists (see prior rounds).
// ------------------------------------------------------------------
struct QLists { unsigned short e[4][7][48]; int cnt[4][7]; };
static constexpr QLists make_lists() {
    QLists L = {};
    for (int q = 0; q < 4; q++) for (int t = 0; t < 7; t++) L.cnt[q][t] = 0;
    for (int i = 0; i < 28; i++) for (int j = 0; j < 28; j++) {
        int dx = j - 14, dy = i - 14;
        int r2 = dx * dx + dy * dy;
        int t = 0, lp = 0;
        if (i < 14) { t = i / 2; lp = (i & 1) * 28 + j; }
        else { t = (27 - i) / 2; lp = 56 + (i - (26 - 2 * ((27 - i) / 2))) * 28 + j; }
        int pp = lp % 56, chunk = lp / 56;
        int word = chunk * 56 + (pp % 4) * 14 + (pp / 4);
        int rad = 0;
        if (r2 == 0) rad = 31;
        else if (r2 <= 361) { rad = 1; while (rad * rad < r2) rad++; }
        else rad = 0;   // corner: contributes to global max only
        bool inq[4] = { dx >= 0 && dy >= 0, dx <= 0 && dy >= 0,
                        dx >= 0 && dy <= 0, dx <= 0 && dy <= 0 };
        for (int q = 0; q < 4; q++) {
            if (rad == 31) { if (q != 0) continue; }
            else if (!inq[q]) continue;
            L.e[q][t][L.cnt[q][t]++] = (unsigned short)(word | (rad << 8));
        }
    }
    return L;
}
static constexpr QLists LISTS = make_lists();

// ------------------------------------------------------------------
// Fully unrolled consume steps: offsets/rad indices fold to
// immediates; ring accumulators r[19] stay in registers.
// ------------------------------------------------------------------
template<int Q, int T, int K, int N>
struct Steps {
    __device__ __forceinline__ static void run(const float* sxc, float* r,
                                               float& gm0, float& cen) {
        constexpr unsigned e = LISTS.e[Q][T][K];
        constexpr int rad = e >> 8;
        float v = sxc[e & 255];
        if constexpr (rad == 31) { cen = v; }
        else if constexpr (rad == 0) { gm0 = fmaxf(gm0, v); }
        else { r[rad - 1] = fmaxf(r[rad - 1], v); }
        Steps<Q, T, K + 1, N>::run(sxc, r, gm0, cen);
    }
};
template<int Q, int T, int N>
struct Steps<Q, T, N, N> {
    __device__ __forceinline__ static void run(const float*, float*, float&, float&) {}
};

// Stage tile T: two 2-row chunks, coalesced LDG.128, transposed
// STS.32 into sx[ch*SXPITCH + chunk*56 + k*14 + f].
template<int T>
__device__ __forceinline__ void stage_tile(const float4* __restrict__ gsrc,
                                           float* sx, int tid) {
#pragma unroll
    for (int c2 = 0; c2 < 2; c2++) {
        const int base = (c2 == 0) ? (14 * T) : ((26 - 2 * T) * 7);
        const int w0c = c2 * 56;
#pragma unroll
        for (int it = 0; it < 4; it++) {
            int m = tid + it * 256;
            if (it < 3 || tid < 128) {
                int ch = m / 14, f = m % 14;
                float4 v = __ldg(gsrc + (size_t)ch * (HW / 4) + base + f);
                float* w = sx + ch * SXPITCH + w0c + f;
                w[0] = v.x; w[14] = v.y; w[28] = v.z; w[42] = v.w;
            }
        }
    }
}

template<int T>
__device__ __forceinline__ void consume_dispatch(int q, const float* sxc, float* r,
                                                 float& gm0, float& cen) {
    if (q == 0)      Steps<0, T, 0, LISTS.cnt[0][T]>::run(sxc, r, gm0, cen);
    else if (q == 1) Steps<1, T, 0, LISTS.cnt[1][T]>::run(sxc, r, gm0, cen);
    else if (q == 2) Steps<2, T, 0, LISTS.cnt[2][T]>::run(sxc, r, gm0, cen);
    else             Steps<3, T, 0, LISTS.cnt[3][T]>::run(sxc, r, gm0, cen);
}

template<int T>
__device__ __forceinline__ void tiles(const float4* __restrict__ gsrc, float* sx,
                                      int tid, int q, const float* sxc, float* r,
                                      float& gm0, float& cen) {
    stage_tile<T>(gsrc, sx, tid);
    __syncthreads();
    consume_dispatch<T>(q, sxc, r, gm0, cen);   // no syncs inside (warp-uniform q)
    __syncthreads();
    if constexpr (T < 6) tiles<T + 1>(gsrc, sx, tid, q, sxc, r, gm0, cen);
}

// ------------------------------------------------------------------
// k1: block = 64 channels x 4 quadrant-threads (256). Ring maxes in
// registers. Epilogue: broadcast center, combine quadrant gm, prefix
// maxes, coalesced state writes, inline squared-norm warp reductions
// -> g_sqpart (deterministic, no atomics).
// ------------------------------------------------------------------
__global__ __launch_bounds__(256) void k1_ringmax(const float* __restrict__ x) {
    __shared__ float sx[64 * SXPITCH];         // 28928 B
    int tid = threadIdx.x;
    int q = tid >> 6;
    int ch = tid & 63;
    int lane = tid & 31;
    int half = (tid >> 5) & 1;
    int bc0 = blockIdx.x * 64;

    const float4* gsrc = (const float4*)(x + (size_t)bc0 * HW);
    float r[19];
#pragma unroll
    for (int i = 0; i < 19; i++) r[i] = -INFINITY;
    float gm0 = -INFINITY, cen = 0.0f;

    tiles<0>(gsrc, sx, tid, q, sx + ch * SXPITCH, r, gm0, cen);

    // ---- epilogue (sx reused; last tiles<> ended with __syncthreads) ----
    float* scen = sx;                 // [64]
    float* sgm = sx + 64;             // [4][64]
    float* spart = sx + 64 + 256;     // [NMASK][2]

    if (q == 0) scen[ch] = cen;
    __syncthreads();
    float centerv = scen[ch];

    float gmq = fmaxf(gm0, centerv);
#pragma unroll
    for (int i = 0; i < 19; i++) gmq = fmaxf(gmq, r[i]);
    sgm[q * 64 + ch] = gmq;
    __syncthreads();

#define WRED(m, val) { float _s = (val) * (val); \
    _s += __shfl_xor_sync(0xffffffffu, _s, 16); \
    _s += __shfl_xor_sync(0xffffffffu, _s, 8); \
    _s += __shfl_xor_sync(0xffffffffu, _s, 4); \
    _s += __shfl_xor_sync(0xffffffffu, _s, 2); \
    _s += __shfl_xor_sync(0xffffffffu, _s, 1); \
    if (lane == 0) spart[(m) * 2 + half] = _s; }

    float* st = g_st + bc0 + ch;
    if (q == 0) {
        float gmf = fmaxf(fmaxf(sgm[ch], sgm[64 + ch]),
                          fmaxf(sgm[128 + ch], sgm[192 + ch]));
        st[0] = centerv;
        st[(size_t)BC_TOTAL] = gmf;
        WRED(0, fmaxf(centerv, 0.0f));
        WRED(153, gmf);
    }

    float c = centerv;
#pragma unroll
    for (int rad = 1; rad <= 19; rad++) {
        float rv = r[rad - 1];
        c = fmaxf(c, rv);
        st[(size_t)(2 + (rad - 1) * 4 + q) * BC_TOTAL] = rv;
        int mb = 1 + (rad - 1) * 8 + q * 2;
        WRED(mb, fmaxf(rv, 0.0f));
        WRED(mb + 1, fmaxf(c, 0.0f));
    }
#undef WRED

    __syncthreads();
    if (tid < NMASK)
        g_sqpart[tid * K1_BLOCKS + blockIdx.x] = spart[tid * 2] + spart[tid * 2 + 1];
}

// ------------------------------------------------------------------
// kf v2: block = 4 quadrant-subs x 64 bc. Sub q reads ONLY its own
// 19 ring planes (zero redundancy, 20 coalesced loads/thread, full
// MLP), runs its private prefix chain, accumulates ring+circle
// terms. Sub 0 folds in center & global-max terms. 4 partials
// combined in smem.
// ------------------------------------------------------------------
__global__ __launch_bounds__(256) void kf_out(float* __restrict__ out) {
    __shared__ float rn[NMASK];
    __shared__ float part[4 * 64];
    int tid = threadIdx.x;
    int blk = blockIdx.x;                      // 512 blocks, 64 bc each
    int b = blk >> 4;                          // 16 k1-blocks per batch b
    if (tid < NMASK) {
        const float* p = g_sqpart + tid * K1_BLOCKS + b * 16;
        float s = 0.0f;
#pragma unroll
        for (int k = 0; k < 16; k++) s += p[k];
        rn[tid] = 1.0f / (sqrtf(s) + 1e-6f);
    }
    __syncthreads();

    int q = tid >> 6;
    int t = tid & 63;
    int bc = blk * 64 + t;
    const float* st = g_st + bc;

    // load all 19 ring values for this quadrant up-front (independent LDGs)
    float rv[19];
#pragma unroll
    for (int rad = 1; rad <= 19; rad++)
        rv[rad - 1] = __ldg(st + (size_t)(2 + (rad - 1) * 4 + q) * BC_TOTAL);

    float centerv = __ldg(st);
    float c = centerv;
    float acc = 0.0f;
#pragma unroll
    for (int rad = 1; rad <= 19; rad++) {
        float r = rv[rad - 1];
        c = fmaxf(c, r);
        int mb = 1 + (rad - 1) * 8 + q * 2;
        acc += fmaxf(r, 0.0f) * rn[mb] + fmaxf(c, 0.0f) * rn[mb + 1];
    }
    if (q == 0) {
        acc += fmaxf(centerv, 0.0f) * rn[0]
             + __ldg(st + (size_t)BC_TOTAL) * rn[153];
    }
    part[q * 64 + t] = acc;
    __syncthreads();
    if (tid < 64) {
        out[blk * 64 + tid] = part[tid] + part[64 + tid] + part[128 + tid] + part[192 + tid];
    }
}

extern "C" void kernel_launch(void* const* d_in, const int* in_sizes, int n_in,
                              void* d_out, int out_size) {
    const float* x = (const float*)d_in[0];
    float* out = (float*)d_out;
    k1_ringmax<<<K1_BLOCKS, 256>>>(x);
    kf_out<<<K1_BLOCKS, 256>>>(out);
}

// round 8
// speedup vs baseline: 1.0017x; 1.0017x over previous
#include <cuda_runtime.h>
#include <math.h>

#define Bv 32
#define Cv 1024
#define BC_TOTAL (Bv * Cv)      // 32768
#define HW 784                  // 28*28
#define NMASK 154               // 153 masks + 1 global-max term
#define K1_BLOCKS 512           // 64 channels per block
#define SXPITCH 113             // words per channel row in staging (odd -> conflict-free)
#define NST 78                  // state floats per (b,c): center, gm, 76 rings

// ---- static device scratch (no allocations allowed) ----
__device__ float g_st[NST * BC_TOTAL];        // compact state, ~10.2 MB
__device__ float g_sqpart[NMASK * K1_BLOCKS]; // per-block partial squared sums
__device__ float g_rn[Bv * NMASK];            // rn[b][m] = 1/(norm+eps), transposed

// ------------------------------------------------------------------
// Compile-time per-(quadrant, tile) pixel lists (see prior rounds).
// ------------------------------------------------------------------
struct QLists { unsigned short e[4][7][48]; int cnt[4][7]; };
static constexpr QLists make_lists() {
    QLists L = {};
    for (int q = 0; q < 4; q++) for (int t = 0; t < 7; t++) L.cnt[q][t] = 0;
    for (int i = 0; i < 28; i++) for (int j = 0; j < 28; j++) {
        int dx = j - 14, dy = i - 14;
        int r2 = dx * dx + dy * dy;
        int t = 0, lp = 0;
        if (i < 14) { t = i / 2; lp = (i & 1) * 28 + j; }
        else { t = (27 - i) / 2; lp = 56 + (i - (26 - 2 * ((27 - i) / 2))) * 28 + j; }
        int pp = lp % 56, chunk = lp / 56;
        int word = chunk * 56 + (pp % 4) * 14 + (pp / 4);
        int rad = 0;
        if (r2 == 0) rad = 31;
        else if (r2 <= 361) { rad = 1; while (rad * rad < r2) rad++; }
        else rad = 0;   // corner: contributes to global max only
        bool inq[4] = { dx >= 0 && dy >= 0, dx <= 0 && dy >= 0,
                        dx >= 0 && dy <= 0, dx <= 0 && dy <= 0 };
        for (int q = 0; q < 4; q++) {
            if (rad == 31) { if (q != 0) continue; }
            else if (!inq[q]) continue;
            L.e[q][t][L.cnt[q][t]++] = (unsigned short)(word | (rad << 8));
        }
    }
    return L;
}
static constexpr QLists LISTS = make_lists();

// ------------------------------------------------------------------
// Fully unrolled consume steps: offsets/rad indices fold to
// immediates; ring accumulators r[19] stay in registers.
// ------------------------------------------------------------------
template<int Q, int T, int K, int N>
struct Steps {
    __device__ __forceinline__ static void run(const float* sxc, float* r,
                                               float& gm0, float& cen) {
        constexpr unsigned e = LISTS.e[Q][T][K];
        constexpr int rad = e >> 8;
        float v = sxc[e & 255];
        if constexpr (rad == 31) { cen = v; }
        else if constexpr (rad == 0) { gm0 = fmaxf(gm0, v); }
        else { r[rad - 1] = fmaxf(r[rad - 1], v); }
        Steps<Q, T, K + 1, N>::run(sxc, r, gm0, cen);
    }
};
template<int Q, int T, int N>
struct Steps<Q, T, N, N> {
    __device__ __forceinline__ static void run(const float*, float*, float&, float&) {}
};

// Stage tile T: two 2-row chunks, coalesced LDG.128, transposed
// STS.32 into sx[ch*SXPITCH + chunk*56 + k*14 + f].
template<int T>
__device__ __forceinline__ void stage_tile(const float4* __restrict__ gsrc,
                                           float* sx, int tid) {
#pragma unroll
    for (int c2 = 0; c2 < 2; c2++) {
        const int base = (c2 == 0) ? (14 * T) : ((26 - 2 * T) * 7);
        const int w0c = c2 * 56;
#pragma unroll
        for (int it = 0; it < 4; it++) {
            int m = tid + it * 256;
            if (it < 3 || tid < 128) {
                int ch = m / 14, f = m % 14;
                float4 v = __ldg(gsrc + (size_t)ch * (HW / 4) + base + f);
                float* w = sx + ch * SXPITCH + w0c + f;
                w[0] = v.x; w[14] = v.y; w[28] = v.z; w[42] = v.w;
            }
        }
    }
}

template<int T>
__device__ __forceinline__ void consume_dispatch(int q, const float* sxc, float* r,
                                                 float& gm0, float& cen) {
    if (q == 0)      Steps<0, T, 0, LISTS.cnt[0][T]>::run(sxc, r, gm0, cen);
    else if (q == 1) Steps<1, T, 0, LISTS.cnt[1][T]>::run(sxc, r, gm0, cen);
    else if (q == 2) Steps<2, T, 0, LISTS.cnt[2][T]>::run(sxc, r, gm0, cen);
    else             Steps<3, T, 0, LISTS.cnt[3][T]>::run(sxc, r, gm0, cen);
}

template<int T>
__device__ __forceinline__ void tiles(const float4* __restrict__ gsrc, float* sx,
                                      int tid, int q, const float* sxc, float* r,
                                      float& gm0, float& cen) {
    stage_tile<T>(gsrc, sx, tid);
    __syncthreads();
    consume_dispatch<T>(q, sxc, r, gm0, cen);   // no syncs inside (warp-uniform q)
    __syncthreads();
    if constexpr (T < 6) tiles<T + 1>(gsrc, sx, tid, q, sxc, r, gm0, cen);
}

// ------------------------------------------------------------------
// k1: block = 64 channels x 4 quadrant-threads (256). Ring maxes in
// registers. Epilogue: broadcast center, combine quadrant gm, prefix
// maxes, coalesced state writes, inline squared-norm warp reductions
// -> g_sqpart (deterministic, no atomics). Unchanged from round 6.
// ------------------------------------------------------------------
__global__ __launch_bounds__(256) void k1_ringmax(const float* __restrict__ x) {
    __shared__ float sx[64 * SXPITCH];         // 28928 B
    int tid = threadIdx.x;
    int q = tid >> 6;
    int ch = tid & 63;
    int lane = tid & 31;
    int half = (tid >> 5) & 1;
    int bc0 = blockIdx.x * 64;

    const float4* gsrc = (const float4*)(x + (size_t)bc0 * HW);
    float r[19];
#pragma unroll
    for (int i = 0; i < 19; i++) r[i] = -INFINITY;
    float gm0 = -INFINITY, cen = 0.0f;

    tiles<0>(gsrc, sx, tid, q, sx + ch * SXPITCH, r, gm0, cen);

    // ---- epilogue (sx reused; last tiles<> ended with __syncthreads) ----
    float* scen = sx;                 // [64]
    float* sgm = sx + 64;             // [4][64]
    float* spart = sx + 64 + 256;     // [NMASK][2]

    if (q == 0) scen[ch] = cen;
    __syncthreads();
    float centerv = scen[ch];

    float gmq = fmaxf(gm0, centerv);
#pragma unroll
    for (int i = 0; i < 19; i++) gmq = fmaxf(gmq, r[i]);
    sgm[q * 64 + ch] = gmq;
    __syncthreads();

#define WRED(m, val) { float _s = (val) * (val); \
    _s += __shfl_xor_sync(0xffffffffu, _s, 16); \
    _s += __shfl_xor_sync(0xffffffffu, _s, 8); \
    _s += __shfl_xor_sync(0xffffffffu, _s, 4); \
    _s += __shfl_xor_sync(0xffffffffu, _s, 2); \
    _s += __shfl_xor_sync(0xffffffffu, _s, 1); \
    if (lane == 0) spart[(m) * 2 + half] = _s; }

    float* st = g_st + bc0 + ch;
    if (q == 0) {
        float gmf = fmaxf(fmaxf(sgm[ch], sgm[64 + ch]),
                          fmaxf(sgm[128 + ch], sgm[192 + ch]));
        st[0] = centerv;
        st[(size_t)BC_TOTAL] = gmf;
        WRED(0, fmaxf(centerv, 0.0f));
        WRED(153, gmf);
    }

    float c = centerv;
#pragma unroll
    for (int rad = 1; rad <= 19; rad++) {
        float rv = r[rad - 1];
        c = fmaxf(c, rv);
        st[(size_t)(2 + (rad - 1) * 4 + q) * BC_TOTAL] = rv;
        int mb = 1 + (rad - 1) * 8 + q * 2;
        WRED(mb, fmaxf(rv, 0.0f));
        WRED(mb + 1, fmaxf(c, 0.0f));
    }
#undef WRED

    __syncthreads();
    if (tid < NMASK)
        g_sqpart[tid * K1_BLOCKS + blockIdx.x] = spart[tid * 2] + spart[tid * 2 + 1];
}

// ------------------------------------------------------------------
// k2_rn: one thread per (b,m). Sums the 16 per-k1-block partials
// (64 B contiguous per thread) and writes g_rn transposed [b][m]
// so kf reads one contiguous 616 B burst per block.
// ------------------------------------------------------------------
__global__ __launch_bounds__(256) void k2_rn() {
    int i = blockIdx.x * 256 + threadIdx.x;       // i = b*NMASK + m
    if (i >= Bv * NMASK) return;
    int b = i / NMASK, m = i % NMASK;
    const float* p = g_sqpart + m * K1_BLOCKS + b * 16;
    float s = 0.0f;
#pragma unroll
    for (int k = 0; k < 16; k++) s += p[k];
    g_rn[i] = 1.0f / (sqrtf(s) + 1e-6f);
}

// ------------------------------------------------------------------
// kf v3: rn precomputed -> preamble is one contiguous 616 B load.
// Block = 4 quadrant-subs x 64 bc; sub q reads only its own 19 ring
// planes (coalesced, full MLP), private prefix chain, ring+circle
// accumulation. Sub 0 folds in center & global-max terms.
// ------------------------------------------------------------------
__global__ __launch_bounds__(256) void kf_out(float* __restrict__ out) {
    __shared__ float rn[NMASK];
    __shared__ float part[4 * 64];
    int tid = threadIdx.x;
    int blk = blockIdx.x;                      // 512 blocks, 64 bc each
    int b = blk >> 4;
    if (tid < NMASK) rn[tid] = __ldg(g_rn + b * NMASK + tid);
    __syncthreads();

    int q = tid >> 6;
    int t = tid & 63;
    int bc = blk * 64 + t;
    const float* st = g_st + bc;

    // load all 19 ring values for this quadrant up-front (independent LDGs)
    float rv[19];
#pragma unroll
    for (int rad = 1; rad <= 19; rad++)
        rv[rad - 1] = __ldg(st + (size_t)(2 + (rad - 1) * 4 + q) * BC_TOTAL);

    float centerv = __ldg(st);
    float c = centerv;
    float acc = 0.0f;
#pragma unroll
    for (int rad = 1; rad <= 19; rad++) {
        float r = rv[rad - 1];
        c = fmaxf(c, r);
        int mb = 1 + (rad - 1) * 8 + q * 2;
        acc += fmaxf(r, 0.0f) * rn[mb] + fmaxf(c, 0.0f) * rn[mb + 1];
    }
    if (q == 0) {
        acc += fmaxf(centerv, 0.0f) * rn[0]
             + __ldg(st + (size_t)BC_TOTAL) * rn[153];
    }
    part[q * 64 + t] = acc;
    __syncthreads();
    if (tid < 64) {
        out[blk * 64 + tid] = part[tid] + part[64 + tid] + part[128 + tid] + part[192 + tid];
    }
}

extern "C" void kernel_launch(void* const* d_in, const int* in_sizes, int n_in,
                              void* d_out, int out_size) {
    const float* x = (const float*)d_in[0];
    float* out = (float*)d_out;
    k1_ringmax<<<K1_BLOCKS, 256>>>(x);
    k2_rn<<<(Bv * NMASK + 255) / 256, 256>>>();
    kf_out<<<K1_BLOCKS, 256>>>(out);
}

// round 9
// speedup vs baseline: 1.0208x; 1.0191x over previous
#include <cuda_runtime.h>
#include <math.h>

#define Bv 32
#define Cv 1024
#define BC_TOTAL (Bv * Cv)      // 32768
#define HW 784                  // 28*28
#define NMASK 154               // 153 masks + 1 global-max term
#define K1_BLOCKS 512           // 64 channels per block
#define SXPITCH 132             // words/channel (== 4 mod 32 -> conflict-free .128 phases)
#define NST 78                  // state floats per (b,c): center, gm, 76 rings

// ---- static device scratch (no allocations allowed) ----
__device__ float g_st[NST * BC_TOTAL];        // compact state, ~10.2 MB
__device__ float g_sqpart[NMASK * K1_BLOCKS]; // per-block partial squared sums
__device__ float g_rn[Bv * NMASK];            // rn[b][m], transposed for kf burst load

// ------------------------------------------------------------------
// Compile-time per-(quadrant, tile) GROUP lists. Tile t stages rows
// {2t,2t+1} (chunk 0) and {26-2t,27-2t} (chunk 1) LINEARLY:
// word = chunk*56 + lr*28 + col. Groups = 4 consecutive pixels
// (float4). Entry = word | c0<<12 | c1<<17 | c2<<22 | c3<<27 where
// code: 0 skip, 1..19 ring rad, 30 corner (gm-only, first containing
// quadrant), 31 center (q0 only). Ring pixels go to EVERY containing
// quadrant (axis pixels belong to 2).
// Quadrants (ref order): q0 (dx>=0,dy>=0) q1 (dx<=0,dy>=0)
//                        q2 (dx>=0,dy<=0) q3 (dx<=0,dy<=0)
// ------------------------------------------------------------------
struct GLists { unsigned int e[4][7][16]; int cnt[4][7]; };
static constexpr GLists make_glists() {
    GLists L = {};
    for (int q = 0; q < 4; q++) for (int t = 0; t < 7; t++) L.cnt[q][t] = 0;
    for (int t = 0; t < 7; t++)
        for (int c2 = 0; c2 < 2; c2++)
            for (int G = 0; G < 14; G++) {
                int codes[4][4] = {};
                bool any[4] = { false, false, false, false };
                for (int k = 0; k < 4; k++) {
                    int pp = 4 * G + k;
                    int lr = pp / 28, col = pp % 28;
                    int i = (c2 == 0) ? (2 * t + lr) : (26 - 2 * t + lr);
                    int dx = col - 14, dy = i - 14;
                    int r2 = dx * dx + dy * dy;
                    if (r2 == 0) { codes[0][k] = 31; any[0] = true; continue; }
                    bool inq[4] = { dx >= 0 && dy >= 0, dx <= 0 && dy >= 0,
                                    dx >= 0 && dy <= 0, dx <= 0 && dy <= 0 };
                    if (r2 > 361) {
                        for (int q = 0; q < 4; q++)
                            if (inq[q]) { codes[q][k] = 30; any[q] = true; break; }
                    } else {
                        int rad = 1; while (rad * rad < r2) rad++;
                        for (int q = 0; q < 4; q++)
                            if (inq[q]) { codes[q][k] = rad; any[q] = true; }
                    }
                }
                int word = c2 * 56 + 4 * G;
                for (int q = 0; q < 4; q++)
                    if (any[q]) {
                        unsigned int e = (unsigned)word
                            | ((unsigned)codes[q][0] << 12) | ((unsigned)codes[q][1] << 17)
                            | ((unsigned)codes[q][2] << 22) | ((unsigned)codes[q][3] << 27);
                        L.e[q][t][L.cnt[q][t]++] = e;
                    }
            }
    return L;
}
static constexpr GLists GL = make_glists();

// ------------------------------------------------------------------
// cp.async helpers
// ------------------------------------------------------------------
__device__ __forceinline__ void cp_async16(unsigned int dst, const float4* src) {
    asm volatile("cp.async.cg.shared.global [%0], [%1], 16;" :: "r"(dst), "l"(src));
}
#define CP_COMMIT() asm volatile("cp.async.commit_group;" ::: "memory")
#define CP_WAIT0()  asm volatile("cp.async.wait_group 0;" ::: "memory")

// ------------------------------------------------------------------
// Consume: fully unrolled; one LDS.128 per group (uniform broadcast),
// per-pixel codes fold to immediates; ring accumulators r[19] in regs.
// ------------------------------------------------------------------
template<int C>
__device__ __forceinline__ void procc(float v, float* r, float& gm0, float& cen) {
    if constexpr (C == 31) { cen = v; }
    else if constexpr (C == 30) { gm0 = fmaxf(gm0, v); }
    else if constexpr (C >= 1) { r[C - 1] = fmaxf(r[C - 1], v); }
}

template<int Q, int T, int K, int N>
struct Steps {
    __device__ __forceinline__ static void run(const float* sxc, float* r,
                                               float& gm0, float& cen) {
        constexpr unsigned e = GL.e[Q][T][K];
        float4 v = *(const float4*)(sxc + (e & 0xFFF));
        procc<((e >> 12) & 31)>(v.x, r, gm0, cen);
        procc<((e >> 17) & 31)>(v.y, r, gm0, cen);
        procc<((e >> 22) & 31)>(v.z, r, gm0, cen);
        procc<((e >> 27) & 31)>(v.w, r, gm0, cen);
        Steps<Q, T, K + 1, N>::run(sxc, r, gm0, cen);
    }
};
template<int Q, int T, int N>
struct Steps<Q, T, N, N> {
    __device__ __forceinline__ static void run(const float*, float*, float&, float&) {}
};

// Stage tile T via cp.async: coalesced 16B copies, linear layout
// sx[ch*SXPITCH + chunk*56 + 4f].
template<int T>
__device__ __forceinline__ void stage_tile(const float4* __restrict__ gsrc,
                                           unsigned int sxa, int tid) {
#pragma unroll
    for (int c2 = 0; c2 < 2; c2++) {
        const int base = (c2 == 0) ? (14 * T) : ((26 - 2 * T) * 7);
        const int w0 = c2 * 56;
#pragma unroll
        for (int it = 0; it < 4; it++) {
            int m = tid + it * 256;
            if (it < 3 || tid < 128) {
                int ch = m / 14, f = m % 14;
                cp_async16(sxa + (unsigned)(ch * SXPITCH + w0 + 4 * f) * 4,
                           gsrc + (size_t)ch * (HW / 4) + base + f);
            }
        }
    }
}

template<int T>
__device__ __forceinline__ void consume_dispatch(int q, const float* sxc, float* r,
                                                 float& gm0, float& cen) {
    if (q == 0)      Steps<0, T, 0, GL.cnt[0][T]>::run(sxc, r, gm0, cen);
    else if (q == 1) Steps<1, T, 0, GL.cnt[1][T]>::run(sxc, r, gm0, cen);
    else if (q == 2) Steps<2, T, 0, GL.cnt[2][T]>::run(sxc, r, gm0, cen);
    else             Steps<3, T, 0, GL.cnt[3][T]>::run(sxc, r, gm0, cen);
}

template<int T>
__device__ __forceinline__ void tiles(const float4* __restrict__ gsrc,
                                      unsigned int sxa, int tid, int q,
                                      const float* sxc, float* r,
                                      float& gm0, float& cen) {
    stage_tile<T>(gsrc, sxa, tid);
    CP_COMMIT();
    CP_WAIT0();
    __syncthreads();
    consume_dispatch<T>(q, sxc, r, gm0, cen);   // no syncs inside (warp-uniform q)
    __syncthreads();
    if constexpr (T < 6) tiles<T + 1>(gsrc, sxa, tid, q, sxc, r, gm0, cen);
}

// ------------------------------------------------------------------
// k1: block = 64 channels x 4 quadrant-threads (256). cp.async
// staging (linear layout), LDS.128 broadcast consume, ring maxes in
// registers. Epilogue unchanged: center broadcast, quadrant gm
// combine, prefix maxes, coalesced state writes, inline squared-norm
// warp reductions -> g_sqpart.
// ------------------------------------------------------------------
__global__ __launch_bounds__(256) void k1_ringmax(const float* __restrict__ x) {
    __shared__ __align__(16) float sx[64 * SXPITCH];   // 33792 B
    int tid = threadIdx.x;
    int q = tid >> 6;
    int ch = tid & 63;
    int lane = tid & 31;
    int half = (tid >> 5) & 1;
    int bc0 = blockIdx.x * 64;

    unsigned int sxa = (unsigned int)__cvta_generic_to_shared(sx);
    const float4* gsrc = (const float4*)(x + (size_t)bc0 * HW);
    float r[19];
#pragma unroll
    for (int i = 0; i < 19; i++) r[i] = -INFINITY;
    float gm0 = -INFINITY, cen = 0.0f;

    tiles<0>(gsrc, sxa, tid, q, sx + ch * SXPITCH, r, gm0, cen);

    // ---- epilogue (sx reused; last tiles<> ended with __syncthreads) ----
    float* scen = sx;                 // [64]
    float* sgm = sx + 64;             // [4][64]
    float* spart = sx + 64 + 256;     // [NMASK][2]

    if (q == 0) scen[ch] = cen;
    __syncthreads();
    float centerv = scen[ch];

    float gmq = fmaxf(gm0, centerv);
#pragma unroll
    for (int i = 0; i < 19; i++) gmq = fmaxf(gmq, r[i]);
    sgm[q * 64 + ch] = gmq;
    __syncthreads();

#define WRED(m, val) { float _s = (val) * (val); \
    _s += __shfl_xor_sync(0xffffffffu, _s, 16); \
    _s += __shfl_xor_sync(0xffffffffu, _s, 8); \
    _s += __shfl_xor_sync(0xffffffffu, _s, 4); \
    _s += __shfl_xor_sync(0xffffffffu, _s, 2); \
    _s += __shfl_xor_sync(0xffffffffu, _s, 1); \
    if (lane == 0) spart[(m) * 2 + half] = _s; }

    float* st = g_st + bc0 + ch;
    if (q == 0) {
        float gmf = fmaxf(fmaxf(sgm[ch], sgm[64 + ch]),
                          fmaxf(sgm[128 + ch], sgm[192 + ch]));
        st[0] = centerv;
        st[(size_t)BC_TOTAL] = gmf;
        WRED(0, fmaxf(centerv, 0.0f));
        WRED(153, gmf);
    }

    float c = centerv;
#pragma unroll
    for (int rad = 1; rad <= 19; rad++) {
        float rv = r[rad - 1];
        c = fmaxf(c, rv);
        st[(size_t)(2 + (rad - 1) * 4 + q) * BC_TOTAL] = rv;
        int mb = 1 + (rad - 1) * 8 + q * 2;
        WRED(mb, fmaxf(rv, 0.0f));
        WRED(mb + 1, fmaxf(c, 0.0f));
    }
#undef WRED

    __syncthreads();
    if (tid < NMASK)
        g_sqpart[tid * K1_BLOCKS + blockIdx.x] = spart[tid * 2] + spart[tid * 2 + 1];
}

// ------------------------------------------------------------------
// k2_rn: one thread per (b,m). Sums the 16 per-k1-block partials and
// writes g_rn transposed [b][m] for kf's contiguous burst.
// ------------------------------------------------------------------
__global__ __launch_bounds__(256) void k2_rn() {
    int i = blockIdx.x * 256 + threadIdx.x;       // i = b*NMASK + m
    if (i >= Bv * NMASK) return;
    int b = i / NMASK, m = i % NMASK;
    const float* p = g_sqpart + m * K1_BLOCKS + b * 16;
    float s = 0.0f;
#pragma unroll
    for (int k = 0; k < 16; k++) s += p[k];
    g_rn[i] = 1.0f / (sqrtf(s) + 1e-6f);
}

// ------------------------------------------------------------------
// kf: block = 4 quadrant-subs x 64 bc. Sub q reads only its own 19
// ring planes (coalesced, full MLP), private prefix chain,
// ring+circle accumulation. Sub 0 folds in center & gm terms.
// ------------------------------------------------------------------
__global__ __launch_bounds__(256) void kf_out(float* __restrict__ out) {
    __shared__ float rn[NMASK];
    __shared__ float part[4 * 64];
    int tid = threadIdx.x;
    int blk = blockIdx.x;                      // 512 blocks, 64 bc each
    int b = blk >> 4;
    if (tid < NMASK) rn[tid] = __ldg(g_rn + b * NMASK + tid);
    __syncthreads();

    int q = tid >> 6;
    int t = tid & 63;
    int bc = blk * 64 + t;
    const float* st = g_st + bc;

    float rv[19];
#pragma unroll
    for (int rad = 1; rad <= 19; rad++)
        rv[rad - 1] = __ldg(st + (size_t)(2 + (rad - 1) * 4 + q) * BC_TOTAL);

    float centerv = __ldg(st);
    float c = centerv;
    float acc = 0.0f;
#pragma unroll
    for (int rad = 1; rad <= 19; rad++) {
        float r = rv[rad - 1];
        c = fmaxf(c, r);
        int mb = 1 + (rad - 1) * 8 + q * 2;
        acc += fmaxf(r, 0.0f) * rn[mb] + fmaxf(c, 0.0f) * rn[mb + 1];
    }
    if (q == 0) {
        acc += fmaxf(centerv, 0.0f) * rn[0]
             + __ldg(st + (size_t)BC_TOTAL) * rn[153];
    }
    part[q * 64 + t] = acc;
    __syncthreads();
    if (tid < 64) {
        out[blk * 64 + tid] = part[tid] + part[64 + tid] + part[128 + tid] + part[192 + tid];
    }
}

extern "C" void kernel_launch(void* const* d_in, const int* in_sizes, int n_in,
                              void* d_out, int out_size) {
    const float* x = (const float*)d_in[0];
    float* out = (float*)d_out;
    k1_ringmax<<<K1_BLOCKS, 256>>>(x);
    k2_rn<<<(Bv * NMASK + 255) / 256, 256>>>();
    kf_out<<<K1_BLOCKS, 256>>>(out);
}

// round 10
// speedup vs baseline: 1.1961x; 1.1717x over previous
#include <cuda_runtime.h>
#include <math.h>

#define Bv 32
#define Cv 1024
#define BC_TOTAL (Bv * Cv)      // 32768
#define HW 784                  // 28*28
#define NMASK 154               // 153 masks + 1 global-max term
#define K1_BLOCKS 512           // 64 channels per block
#define SXPITCH 132             // words/channel (== 4 mod 32 -> conflict-free .128 phases)
#define BUFW (64 * SXPITCH)     // words per buffer
#define K1_SMEM (2 * BUFW * 4)  // 67584 B (double buffer)
#define NST 78                  // state floats per (b,c): center, gm, 76 rings

// ---- static device scratch (no allocations allowed) ----
__device__ float g_st[NST * BC_TOTAL];        // compact state, ~10.2 MB
__device__ float g_sqpart[NMASK * K1_BLOCKS]; // per-block partial squared sums
__device__ float g_rn[Bv * NMASK];            // rn[b][m], transposed for kf burst load

// ------------------------------------------------------------------
// Compile-time per-(quadrant, tile) GROUP lists. Tile t covers rows
// {2t,2t+1} (chunk 0) and {26-2t,27-2t} (chunk 1), stored LINEARLY:
// word = chunk*56 + lr*28 + col. Entry = word | c0<<12 | c1<<17 |
// c2<<22 | c3<<27; code: 0 skip, 1..19 ring rad, 30 corner (gm-only,
// first containing quadrant), 31 center (q0 only).
// Quadrants (ref order): q0 (dx>=0,dy>=0) q1 (dx<=0,dy>=0)
//                        q2 (dx>=0,dy<=0) q3 (dx<=0,dy<=0)
// ------------------------------------------------------------------
struct GLists { unsigned int e[4][7][16]; int cnt[4][7]; };
static constexpr GLists make_glists() {
    GLists L = {};
    for (int q = 0; q < 4; q++) for (int t = 0; t < 7; t++) L.cnt[q][t] = 0;
    for (int t = 0; t < 7; t++)
        for (int c2 = 0; c2 < 2; c2++)
            for (int G = 0; G < 14; G++) {
                int codes[4][4] = {};
                bool any[4] = { false, false, false, false };
                for (int k = 0; k < 4; k++) {
                    int pp = 4 * G + k;
                    int lr = pp / 28, col = pp % 28;
                    int i = (c2 == 0) ? (2 * t + lr) : (26 - 2 * t + lr);
                    int dx = col - 14, dy = i - 14;
                    int r2 = dx * dx + dy * dy;
                    if (r2 == 0) { codes[0][k] = 31; any[0] = true; continue; }
                    bool inq[4] = { dx >= 0 && dy >= 0, dx <= 0 && dy >= 0,
                                    dx >= 0 && dy <= 0, dx <= 0 && dy <= 0 };
                    if (r2 > 361) {
                        for (int q = 0; q < 4; q++)
                            if (inq[q]) { codes[q][k] = 30; any[q] = true; break; }
                    } else {
                        int rad = 1; while (rad * rad < r2) rad++;
                        for (int q = 0; q < 4; q++)
                            if (inq[q]) { codes[q][k] = rad; any[q] = true; }
                    }
                }
                int word = c2 * 56 + 4 * G;
                for (int q = 0; q < 4; q++)
                    if (any[q]) {
                        unsigned int e = (unsigned)word
                            | ((unsigned)codes[q][0] << 12) | ((unsigned)codes[q][1] << 17)
                            | ((unsigned)codes[q][2] << 22) | ((unsigned)codes[q][3] << 27);
                        L.e[q][t][L.cnt[q][t]++] = e;
                    }
            }
    return L;
}
static constexpr GLists GL = make_glists();

// ------------------------------------------------------------------
// cp.async helpers
// ------------------------------------------------------------------
__device__ __forceinline__ void cp_async16(unsigned int dst, const float4* src) {
    asm volatile("cp.async.cg.shared.global [%0], [%1], 16;" :: "r"(dst), "l"(src));
}
#define CP_COMMIT() asm volatile("cp.async.commit_group;" ::: "memory")
template<int N>
__device__ __forceinline__ void cp_wait() {
    asm volatile("cp.async.wait_group %0;" :: "n"(N) : "memory");
}

// ------------------------------------------------------------------
// Consume: fully unrolled; one LDS.128 per group (uniform broadcast),
// per-pixel codes fold to immediates; ring accumulators r[19] in regs.
// ------------------------------------------------------------------
template<int C>
__device__ __forceinline__ void procc(float v, float* r, float& gm0, float& cen) {
    if constexpr (C == 31) { cen = v; }
    else if constexpr (C == 30) { gm0 = fmaxf(gm0, v); }
    else if constexpr (C >= 1) { r[C - 1] = fmaxf(r[C - 1], v); }
}

template<int Q, int T, int K, int N>
struct Steps {
    __device__ __forceinline__ static void run(const float* sxc, float* r,
                                               float& gm0, float& cen) {
        constexpr unsigned e = GL.e[Q][T][K];
        float4 v = *(const float4*)(sxc + (e & 0xFFF));
        procc<((e >> 12) & 31)>(v.x, r, gm0, cen);
        procc<((e >> 17) & 31)>(v.y, r, gm0, cen);
        procc<((e >> 22) & 31)>(v.z, r, gm0, cen);
        procc<((e >> 27) & 31)>(v.w, r, gm0, cen);
        Steps<Q, T, K + 1, N>::run(sxc, r, gm0, cen);
    }
};
template<int Q, int T, int N>
struct Steps<Q, T, N, N> {
    __device__ __forceinline__ static void run(const float*, float*, float&, float&) {}
};

// Stage tile T via cp.async into buffer buf: coalesced 16B copies,
// linear layout sx[buf*BUFW + ch*SXPITCH + chunk*56 + 4f].
template<int T>
__device__ __forceinline__ void stage_tile(const float4* __restrict__ gsrc,
                                           unsigned int sxa, int tid) {
    const unsigned int boff = (unsigned)((T & 1) * BUFW) * 4;
#pragma unroll
    for (int c2 = 0; c2 < 2; c2++) {
        const int base = (c2 == 0) ? (14 * T) : ((26 - 2 * T) * 7);
        const int w0 = c2 * 56;
#pragma unroll
        for (int it = 0; it < 4; it++) {
            int m = tid + it * 256;
            if (it < 3 || tid < 128) {
                int ch = m / 14, f = m % 14;
                cp_async16(sxa + boff + (unsigned)(ch * SXPITCH + w0 + 4 * f) * 4,
                           gsrc + (size_t)ch * (HW / 4) + base + f);
            }
        }
    }
    CP_COMMIT();
}

template<int T>
__device__ __forceinline__ void consume_dispatch(int q, const float* sxc, float* r,
                                                 float& gm0, float& cen) {
    if (q == 0)      Steps<0, T, 0, GL.cnt[0][T]>::run(sxc, r, gm0, cen);
    else if (q == 1) Steps<1, T, 0, GL.cnt[1][T]>::run(sxc, r, gm0, cen);
    else if (q == 2) Steps<2, T, 0, GL.cnt[2][T]>::run(sxc, r, gm0, cen);
    else             Steps<3, T, 0, GL.cnt[3][T]>::run(sxc, r, gm0, cen);
}

// Pipelined tiles: stage T+1 before waiting on T (wait_group 1 keeps
// one group in flight); consume T from its buffer; tail uses wait 0.
template<int T>
__device__ __forceinline__ void tiles(const float4* __restrict__ gsrc,
                                      unsigned int sxa, float* sx, int tid, int q,
                                      int ch, float* r, float& gm0, float& cen) {
    if constexpr (T < 6) {
        stage_tile<T + 1>(gsrc, sxa, tid);
        cp_wait<1>();
    } else {
        cp_wait<0>();
    }
    __syncthreads();
    consume_dispatch<T>(q, sx + (T & 1) * BUFW + ch * SXPITCH, r, gm0, cen);
    __syncthreads();
    if constexpr (T < 6) tiles<T + 1>(gsrc, sxa, sx, tid, q, ch, r, gm0, cen);
}

// ------------------------------------------------------------------
// k1: block = 64 channels x 4 quadrant-threads (256). Double-buffered
// cp.async staging, LDS.128 broadcast consume, ring maxes in regs.
// Epilogue: center broadcast, quadrant gm combine, prefix maxes,
// coalesced state writes, inline squared-norm warp reductions.
// ------------------------------------------------------------------
__global__ __launch_bounds__(256) void k1_ringmax(const float* __restrict__ x) {
    extern __shared__ __align__(16) float sx[];        // 2 x 33792 B
    int tid = threadIdx.x;
    int q = tid >> 6;
    int ch = tid & 63;
    int lane = tid & 31;
    int half = (tid >> 5) & 1;
    int bc0 = blockIdx.x * 64;

    unsigned int sxa = (unsigned int)__cvta_generic_to_shared(sx);
    const float4* gsrc = (const float4*)(x + (size_t)bc0 * HW);
    float r[19];
#pragma unroll
    for (int i = 0; i < 19; i++) r[i] = -INFINITY;
    float gm0 = -INFINITY, cen = 0.0f;

    stage_tile<0>(gsrc, sxa, tid);
    tiles<0>(gsrc, sxa, sx, tid, q, ch, r, gm0, cen);

    // ---- epilogue (sx reused; last tiles<> ended with __syncthreads) ----
    float* scen = sx;                 // [64]
    float* sgm = sx + 64;             // [4][64]
    float* spart = sx + 64 + 256;     // [NMASK][2]

    if (q == 0) scen[ch] = cen;
    __syncthreads();
    float centerv = scen[ch];

    float gmq = fmaxf(gm0, centerv);
#pragma unroll
    for (int i = 0; i < 19; i++) gmq = fmaxf(gmq, r[i]);
    sgm[q * 64 + ch] = gmq;
    __syncthreads();

#define WRED(m, val) { float _s = (val) * (val); \
    _s += __shfl_xor_sync(0xffffffffu, _s, 16); \
    _s += __shfl_xor_sync(0xffffffffu, _s, 8); \
    _s += __shfl_xor_sync(0xffffffffu, _s, 4); \
    _s += __shfl_xor_sync(0xffffffffu, _s, 2); \
    _s += __shfl_xor_sync(0xffffffffu, _s, 1); \
    if (lane == 0) spart[(m) * 2 + half] = _s; }

    float* st = g_st + bc0 + ch;
    if (q == 0) {
        float gmf = fmaxf(fmaxf(sgm[ch], sgm[64 + ch]),
                          fmaxf(sgm[128 + ch], sgm[192 + ch]));
        st[0] = centerv;
        st[(size_t)BC_TOTAL] = gmf;
        WRED(0, fmaxf(centerv, 0.0f));
        WRED(153, gmf);
    }

    float c = centerv;
#pragma unroll
    for (int rad = 1; rad <= 19; rad++) {
        float rv = r[rad - 1];
        c = fmaxf(c, rv);
        st[(size_t)(2 + (rad - 1) * 4 + q) * BC_TOTAL] = rv;
        int mb = 1 + (rad - 1) * 8 + q * 2;
        WRED(mb, fmaxf(rv, 0.0f));
        WRED(mb + 1, fmaxf(c, 0.0f));
    }
#undef WRED

    __syncthreads();
    if (tid < NMASK)
        g_sqpart[tid * K1_BLOCKS + blockIdx.x] = spart[tid * 2] + spart[tid * 2 + 1];
}

// ------------------------------------------------------------------
// k2_rn: one thread per (b,m). Sums the 16 per-k1-block partials and
// writes g_rn transposed [b][m] for kf's contiguous burst.
// ------------------------------------------------------------------
__global__ __launch_bounds__(256) void k2_rn() {
    int i = blockIdx.x * 256 + threadIdx.x;       // i = b*NMASK + m
    if (i >= Bv * NMASK) return;
    int b = i / NMASK, m = i % NMASK;
    const float* p = g_sqpart + m * K1_BLOCKS + b * 16;
    float s = 0.0f;
#pragma unroll
    for (int k = 0; k < 16; k++) s += p[k];
    g_rn[i] = 1.0f / (sqrtf(s) + 1e-6f);
}

// ------------------------------------------------------------------
// kf: block = 4 quadrant-subs x 64 bc. Sub q reads only its own 19
// ring planes (coalesced, full MLP), private prefix chain,
// ring+circle accumulation. Sub 0 folds in center & gm terms.
// ------------------------------------------------------------------
__global__ __launch_bounds__(256) void kf_out(float* __restrict__ out) {
    __shared__ float rn[NMASK];
    __shared__ float part[4 * 64];
    int tid = threadIdx.x;
    int blk = blockIdx.x;                      // 512 blocks, 64 bc each
    int b = blk >> 4;
    if (tid < NMASK) rn[tid] = __ldg(g_rn + b * NMASK + tid);
    __syncthreads();

    int q = tid >> 6;
    int t = tid & 63;
    int bc = blk * 64 + t;
    const float* st = g_st + bc;

    float rv[19];
#pragma unroll
    for (int rad = 1; rad <= 19; rad++)
        rv[rad - 1] = __ldg(st + (size_t)(2 + (rad - 1) * 4 + q) * BC_TOTAL);

    float centerv = __ldg(st);
    float c = centerv;
    float acc = 0.0f;
#pragma unroll
    for (int rad = 1; rad <= 19; rad++) {
        float r = rv[rad - 1];
        c = fmaxf(c, r);
        int mb = 1 + (rad - 1) * 8 + q * 2;
        acc += fmaxf(r, 0.0f) * rn[mb] + fmaxf(c, 0.0f) * rn[mb + 1];
    }
    if (q == 0) {
        acc += fmaxf(centerv, 0.0f) * rn[0]
             + __ldg(st + (size_t)BC_TOTAL) * rn[153];
    }
    part[q * 64 + t] = acc;
    __syncthreads();
    if (tid < 64) {
        out[blk * 64 + tid] = part[tid] + part[64 + tid] + part[128 + tid] + part[192 + tid];
    }
}

extern "C" void kernel_launch(void* const* d_in, const int* in_sizes, int n_in,
                              void* d_out, int out_size) {
    const float* x = (const float*)d_in[0];
    float* out = (float*)d_out;
    cudaFuncSetAttribute(k1_ringmax, cudaFuncAttributeMaxDynamicSharedMemorySize, K1_SMEM);
    k1_ringmax<<<K1_BLOCKS, 256, K1_SMEM>>>(x);
    k2_rn<<<(Bv * NMASK + 255) / 256, 256>>>();
    kf_out<<<K1_BLOCKS, 256>>>(out);
}